// round 16
// baseline (speedup 1.0000x reference)
#include <cuda_runtime.h>
#include <cuda_fp16.h>
#include <math.h>
#include <stdint.h>

#define BH   24
#define TT   2048
#define NN   256
#define CC   128
#define NCH  16

// ---------------- device scratch ----------------------------------------------
__device__ float g_tabc[TT * (NN/2)];
__device__ float g_tabs[TT * (NN/2)];
__device__ __half g_S16[BH*NCH*NN*NN];        // per-chunk K^T V, fp16
__device__ __half g_Sh [BH*NCH*NN*NN];        // exclusive prefix, fp16

// ---------------- PTX helpers ---------------------------------------------------
__device__ __forceinline__ uint32_t smem_u32(const void* p) {
    uint32_t a;
    asm("{ .reg .u64 t; cvta.to.shared.u64 t, %1; cvt.u32.u64 %0, t; }" : "=r"(a) : "l"(p));
    return a;
}
__device__ __forceinline__ void cpa16(uint32_t s, const void* g) {
    asm volatile("cp.async.cg.shared.global [%0], [%1], 16;" :: "r"(s), "l"(g));
}
#define CP_COMMIT() asm volatile("cp.async.commit_group;" ::: "memory")
#define CP_WAIT0()  asm volatile("cp.async.wait_group 0;" ::: "memory")
#define CP_WAIT1()  asm volatile("cp.async.wait_group 1;" ::: "memory")

__device__ __forceinline__ void ldsm4(uint32_t* r, uint32_t a) {
    asm volatile("ldmatrix.sync.aligned.m8n8.x4.shared.b16 {%0,%1,%2,%3}, [%4];"
        : "=r"(r[0]), "=r"(r[1]), "=r"(r[2]), "=r"(r[3]) : "r"(a));
}
__device__ __forceinline__ void ldsm4t(uint32_t* r, uint32_t a) {
    asm volatile("ldmatrix.sync.aligned.m8n8.x4.trans.shared.b16 {%0,%1,%2,%3}, [%4];"
        : "=r"(r[0]), "=r"(r[1]), "=r"(r[2]), "=r"(r[3]) : "r"(a));
}
__device__ __forceinline__ void mma_f16(float* d, const uint32_t* a, const uint32_t* b) {
    asm volatile("mma.sync.aligned.m16n8k16.row.col.f32.f16.f16.f32 "
        "{%0,%1,%2,%3}, {%4,%5,%6,%7}, {%8,%9}, {%0,%1,%2,%3};"
        : "+f"(d[0]), "+f"(d[1]), "+f"(d[2]), "+f"(d[3])
        : "r"(a[0]), "r"(a[1]), "r"(a[2]), "r"(a[3]), "r"(b[0]), "r"(b[1]));
}

// ---------------- fp16 cvt helpers -----------------------------------------------
__device__ __forceinline__ uint32_t cvtH2(float x, float y) {
    __half2 H = __floats2half2_rn(x, y);
    return *(uint32_t*)&H;
}
__device__ __forceinline__ uint4 rope_cvt8_cs(const float* __restrict__ src,
                                              float4 c, float4 s) {
    float4 a = *(const float4*)(src);
    float4 b = *(const float4*)(src + 4);
    uint4 h;
    h.x = cvtH2(a.x*c.x - a.y*s.x, a.y*c.x + a.x*s.x);
    h.y = cvtH2(a.z*c.y - a.w*s.y, a.w*c.y + a.z*s.y);
    h.z = cvtH2(b.x*c.z - b.y*s.z, b.y*c.z + b.x*s.z);
    h.w = cvtH2(b.z*c.w - b.w*s.w, b.w*c.w + b.z*s.w);
    return h;
}
__device__ __forceinline__ uint4 rope_cvt8(const float* __restrict__ src, int t, int f) {
    float4 c = *(const float4*)(g_tabc + t * 128 + (f >> 1));
    float4 s = *(const float4*)(g_tabs + t * 128 + (f >> 1));
    return rope_cvt8_cs(src, c, s);
}
__device__ __forceinline__ uint4 cvt8(const float* __restrict__ src) {
    float4 a = *(const float4*)(src);
    float4 b = *(const float4*)(src + 4);
    uint4 h;
    h.x = cvtH2(a.x, a.y); h.y = cvtH2(a.z, a.w);
    h.z = cvtH2(b.x, b.y); h.w = cvtH2(b.z, b.w);
    return h;
}

// ---------------- kernel 1: RoPE phase tables -----------------------------------
__global__ void k_tables() {
    int id = blockIdx.x * blockDim.x + threadIdx.x;
    if (id >= TT * (NN/2)) return;
    int t = id >> 7;
    int j = id & 127;
    double fr_d = exp2(-(double)j / 8.0) / (2.0 * 3.14159265358979323846);
    float f32 = (float)fr_d;
    float ph  = (float)t * f32;
    ph = ph - floorf(ph);
    float ang = ph * 6.28318530717958647692f;
    double angd = (double)ang;
    g_tabc[id] = (float)cos(angd);
    g_tabs[id] = (float)sin(angd);
}

// ---------------- kernel 2: chunk KV state, V resident, split prologue ----------
#define KVV_SM   0
#define KVA_0    67584
#define KV_BUF_A 17408
#define SMEM_KV  102400

__global__ void __launch_bounds__(512, 1) k_kv(const float* __restrict__ K,
                                               const float* __restrict__ V) {
    extern __shared__ char sm[];
    uint32_t sb = smem_u32(sm);
    int tid = threadIdx.x, lane = tid & 31, wid = tid >> 5;
    int wm = wid >> 2, wn = wid & 3;
    int bx = blockIdx.x;
    int bh = bx / 15, ch = bx % 15;
    int t0 = ch * CC;
    int l16 = lane >> 4, lmod8 = lane & 7, l8 = (lane >> 3) & 1;
    int lq = lane >> 2, lr2 = (lane & 3) * 2;

    const float* Kp = K + (size_t)(bh * TT + t0) * NN;
    const float* Vp = V + (size_t)(bh * TT + t0) * NN;

    int ar = tid >> 4, ac8 = tid & 15;
    uint32_t a_so = (uint32_t)(ar * 272 + ac8 * 16);
    int vvr = tid >> 5, vvc = tid & 31;

    uint4 ah4a, ah4b;
    auto loadA = [&](int m0g, int sl) {
        int r0 = sl * 64;
        int f = m0g * 128 + ac8 * 8;
        ah4a = rope_cvt8(Kp + (size_t)(r0 + ar) * NN + f,      t0 + r0 + ar,      f);
        ah4b = rope_cvt8(Kp + (size_t)(r0 + ar + 32) * NN + f, t0 + r0 + ar + 32, f);
    };
    auto storeA = [&](int buf) {
        char* ab = sm + KVA_0 + buf * KV_BUF_A;
        *(uint4*)(ab + a_so) = ah4a;
        *(uint4*)(ab + 8704 + a_so) = ah4b;
    };

    // stage A(0,0) + V rows 0..63 only (first MMA tile needs only these)
    loadA(0, 0);
    storeA(0);
#pragma unroll
    for (int g = 0; g < 4; g++) {
        int idx = tid + g * 512;
        int r = idx >> 5, c8 = idx & 31;
        uint4 vv = cvt8(Vp + (size_t)r * NN + c8 * 8);
        *(uint4*)(sm + KVV_SM + r * 528 + c8 * 16) = vv;
    }
    __syncthreads();

    float acc[2][8][4];
#pragma unroll
    for (int a = 0; a < 2; a++)
#pragma unroll
        for (int b = 0; b < 8; b++)
#pragma unroll
            for (int c = 0; c < 4; c++) acc[a][b][c] = 0.f;

    float4 vraw[8];
    for (int it = 0; it < 4; it++) {
        int m0g = it >> 1, sl = it & 1;
        if (it == 0) {
            loadA(0, 1);
            // raw-load V rows 64..127 (cvt+store after this tile's MMAs)
#pragma unroll
            for (int g = 0; g < 4; g++) {
                int r = 64 + vvr + 16 * g;
                vraw[2*g]   = *(const float4*)(Vp + (size_t)r * NN + vvc * 8);
                vraw[2*g+1] = *(const float4*)(Vp + (size_t)r * NN + vvc * 8 + 4);
            }
        } else if (it < 3) loadA((it + 1) >> 1, (it + 1) & 1);
        uint32_t ab = sb + KVA_0 + (it & 1) * KV_BUF_A;
#pragma unroll
        for (int k0 = 0; k0 < 64; k0 += 16) {
            uint32_t ah[2][4];
#pragma unroll
            for (int mt = 0; mt < 2; mt++) {
                uint32_t off = (uint32_t)(((k0 + lmod8 + 8 * l16) * 136 +
                                           wm * 32 + mt * 16 + 8 * l8) * 2);
                ldsm4t(ah[mt], ab + off);
            }
#pragma unroll
            for (int np = 0; np < 4; np++) {
                uint32_t bh2[4];
                uint32_t off = (uint32_t)(((sl * 64 + k0 + lmod8 + 8 * l8) * 264 +
                                           wn * 64 + np * 16 + 8 * l16) * 2);
                ldsm4t(bh2, sb + KVV_SM + off);
#pragma unroll
                for (int mt = 0; mt < 2; mt++) {
                    mma_f16(acc[mt][2*np],   ah[mt], bh2);
                    mma_f16(acc[mt][2*np+1], ah[mt], bh2 + 2);
                }
            }
        }
        if (sl == 1) {
            __half* Sp = g_S16 + (size_t)(bh * NCH + ch) * (NN * NN);
#pragma unroll
            for (int mt = 0; mt < 2; mt++)
#pragma unroll
                for (int nt = 0; nt < 8; nt++)
#pragma unroll
                    for (int h = 0; h < 2; h++) {
                        int rr = m0g * 128 + wm * 32 + mt * 16 + lq + 8 * h;
                        int cc = wn * 64 + nt * 8 + lr2;
                        *(uint32_t*)(Sp + (size_t)rr * NN + cc) =
                            cvtH2(acc[mt][nt][2*h], acc[mt][nt][2*h+1]);
                    }
#pragma unroll
            for (int a = 0; a < 2; a++)
#pragma unroll
                for (int b = 0; b < 8; b++)
#pragma unroll
                    for (int c = 0; c < 4; c++) acc[a][b][c] = 0.f;
        }
        if (it == 0) {
            // cvt + store V rows 64..127
#pragma unroll
            for (int g = 0; g < 4; g++) {
                int r = 64 + vvr + 16 * g;
                uint4 vv;
                vv.x = cvtH2(vraw[2*g].x,   vraw[2*g].y);
                vv.y = cvtH2(vraw[2*g].z,   vraw[2*g].w);
                vv.z = cvtH2(vraw[2*g+1].x, vraw[2*g+1].y);
                vv.w = cvtH2(vraw[2*g+1].z, vraw[2*g+1].w);
                *(uint4*)(sm + KVV_SM + r * 528 + vvc * 16) = vv;
            }
            storeA(1);
            __syncthreads();
        } else if (it < 3) { storeA((it + 1) & 1); __syncthreads(); }
    }
}

// ---------------- kernel 3: exclusive prefix scan (uint4, fp32 accum) -----------
__global__ void k_scan() {
    int g = blockIdx.x * blockDim.x + threadIdx.x;
    if (g >= BH * NN * NN / 8) return;
    int bh = g >> 13;
    int e8 = (g & 8191) << 3;
    size_t base = (size_t)bh * NCH * (NN * NN) + e8;
    uint4 vals[NCH - 1];
#pragma unroll
    for (int i = 0; i < NCH - 1; i++)
        vals[i] = *(const uint4*)(g_S16 + base + (size_t)i * (NN * NN));
    float r[8];
#pragma unroll
    for (int j = 0; j < 8; j++) r[j] = 0.f;
#pragma unroll
    for (int i = 0; i < NCH; i++) {
        size_t p = base + (size_t)i * (NN * NN);
        uint4 H;
        H.x = cvtH2(r[0], r[1]); H.y = cvtH2(r[2], r[3]);
        H.z = cvtH2(r[4], r[5]); H.w = cvtH2(r[6], r[7]);
        *(uint4*)(g_Sh + p) = H;
        if (i < NCH - 1) {
            float2 a0 = __half22float2(*(__half2*)&vals[i].x);
            float2 a1 = __half22float2(*(__half2*)&vals[i].y);
            float2 a2 = __half22float2(*(__half2*)&vals[i].z);
            float2 a3 = __half22float2(*(__half2*)&vals[i].w);
            r[0] += a0.x; r[1] += a0.y; r[2] += a1.x; r[3] += a1.y;
            r[4] += a2.x; r[5] += a2.y; r[6] += a3.x; r[7] += a3.y;
        }
    }
}

// ---------------- kernel 4: Out = QR@S_pref + strict_tril(QR@KR^T)@V ------------
#define AT_QBUF  18432
#define AT_B0    73728
#define AT_BUF_B 33792
#define AT_PH    141312
#define SMEM_ATTN 176128

__global__ void __launch_bounds__(512, 1) k_attn(const float* __restrict__ Q,
                                                 const float* __restrict__ K,
                                                 const float* __restrict__ V,
                                                 float* __restrict__ out) {
    extern __shared__ char sm[];
    uint32_t sb = smem_u32(sm);
    int tid = threadIdx.x, lane = tid & 31, wid = tid >> 5;
    int wm = wid >> 2, wn = wid & 3;
    int bh = blockIdx.x >> 4, ch = 15 - (blockIdx.x & 15);
    int t0 = ch * CC;
    int lm16 = lane & 15, l16 = lane >> 4, lmod8 = lane & 7, l8 = (lane >> 3) & 1;
    int lq = lane >> 2, lr2 = (lane & 3) * 2;

    const float* Qp = Q + (size_t)(bh * TT + t0) * NN;
    const float* Kp = K + (size_t)(bh * TT + t0) * NN;
    const float* Vp = V + (size_t)(bh * TT + t0) * NN;
    const __half* Sh = g_Sh + (size_t)(bh * NCH + ch) * (NN * NN);

    int sr = tid >> 2, sc8 = tid & 3;
    uint32_t s_so1 = (uint32_t)((sr * 72 + sc8 * 8) * 2);
    uint32_t s_so2 = (uint32_t)((sr * 72 + 32 + sc8 * 8) * 2);
    int vr = tid >> 5, vc8 = tid & 31;
    uint32_t v_so = (uint32_t)(vr * 528 + vc8 * 16);

    // zero the 4 never-written 16x16 tiles on the 32-block diagonals of P
    {
        int tile = tid >> 7, r = (tid >> 3) & 15, c2 = tid & 7;
        int row = tile * 32 + r, col = tile * 32 + 16 + c2 * 2;
        *(uint32_t*)(sm + AT_PH + (row * 136 + col) * 2) = 0u;
    }

    uint4 qa, qb, ka, kb;
    auto loadQK = [&](int sl) {
        int f1 = sl * 64 + sc8 * 8;
        float4 c1 = *(const float4*)(g_tabc + (t0 + sr) * 128 + (f1 >> 1));
        float4 s1 = *(const float4*)(g_tabs + (t0 + sr) * 128 + (f1 >> 1));
        float4 c2 = *(const float4*)(g_tabc + (t0 + sr) * 128 + (f1 >> 1) + 16);
        float4 s2 = *(const float4*)(g_tabs + (t0 + sr) * 128 + (f1 >> 1) + 16);
        qa = rope_cvt8_cs(Qp + (size_t)sr * NN + f1, c1, s1);
        qb = rope_cvt8_cs(Qp + (size_t)sr * NN + f1 + 32, c2, s2);
        ka = rope_cvt8_cs(Kp + (size_t)sr * NN + f1, c1, s1);
        kb = rope_cvt8_cs(Kp + (size_t)sr * NN + f1 + 32, c2, s2);
    };
    auto storeQK = [&](int sl) {
        char* qbuf = sm + sl * AT_QBUF;
        *(uint4*)(qbuf + s_so1) = qa;
        *(uint4*)(qbuf + s_so2) = qb;
        char* kbuf = sm + AT_B0 + (sl & 1) * AT_BUF_B;
        *(uint4*)(kbuf + s_so1) = ka;
        *(uint4*)(kbuf + s_so2) = kb;
    };
    auto cpS = [&](int buf, int sl) {
        uint32_t bb = sb + AT_B0 + buf * AT_BUF_B;
        int f0 = sl * 64;
#pragma unroll
        for (int v = tid; v < 2048; v += 512) {
            int r = v >> 5, c8 = v & 31;
            uint32_t so = (uint32_t)(r * 528 + c8 * 16);
            cpa16(bb + so, Sh + (size_t)(f0 + r) * NN + c8 * 8);
        }
    };
    uint4 vh0, vh1;
    auto loadV3 = [&](int sl) {
        vh0 = cvt8(Vp + (size_t)(sl * 32 + vr) * NN + vc8 * 8);
        vh1 = cvt8(Vp + (size_t)(sl * 32 + vr + 16) * NN + vc8 * 8);
    };
    auto storeV3 = [&](int buf) {
        char* bb = sm + AT_B0 + buf * AT_BUF_B;
        *(uint4*)(bb + v_so) = vh0;
        *(uint4*)(bb + 8448 + v_so) = vh1;
    };

    // stage-1 tile assignment: 36 lower-triangle 16x16 tiles over 16 warps
    int ntile = (wid < 4) ? 3 : 2;
    int trs[3], tcs[3];
#pragma unroll
    for (int j = 0; j < 3; j++) {
        if (j < ntile) {
            int f = wid + 16 * j;
            int tr = 0;
            while ((tr + 1) * (tr + 2) / 2 <= f) tr++;
            trs[j] = tr;
            tcs[j] = f - tr * (tr + 1) / 2;
        } else { trs[j] = 0; tcs[j] = 0; }
    }

    // ======== Stage 1: P = QR @ KR^T, 16x16 tiles, all warps ===================
    float acc1[3][2][4];
#pragma unroll
    for (int a = 0; a < 3; a++)
#pragma unroll
        for (int b = 0; b < 2; b++)
#pragma unroll
            for (int c = 0; c < 4; c++) acc1[a][b][c] = 0.f;

    loadQK(0);
    storeQK(0);
    __syncthreads();
    for (int sl = 0; sl < 4; sl++) {
        if (sl < 3) loadQK(sl + 1);
        else if (ch > 0) { cpS(0, 0); CP_COMMIT(); }
        uint32_t ab = sb + sl * AT_QBUF;
        uint32_t bb = sb + AT_B0 + (sl & 1) * AT_BUF_B;
#pragma unroll
        for (int k0 = 0; k0 < 64; k0 += 16) {
#pragma unroll
            for (int j = 0; j < 3; j++) {
                if (j < ntile) {
                    uint32_t af[4], bf[4];
                    ldsm4(af, ab + (uint32_t)(((trs[j] * 16 + lm16) * 72 +
                                               k0 + 8 * l16) * 2));
                    ldsm4(bf, bb + (uint32_t)(((tcs[j] * 16 + lmod8 + 8 * l16) * 72 +
                                               k0 + 8 * l8) * 2));
                    mma_f16(acc1[j][0], af, bf);
                    mma_f16(acc1[j][1], af, bf + 2);
                }
            }
        }
        if (sl < 3) { storeQK(sl + 1); __syncthreads(); }
    }
    __syncthreads();
    if (ch > 0) { cpS(1, 1); CP_COMMIT(); }
    else loadV3(0);

    // mask (strict lower triangle) + fp16 cvt into smem P
#pragma unroll
    for (int j = 0; j < 3; j++) {
        if (j < ntile) {
#pragma unroll
            for (int np = 0; np < 2; np++)
#pragma unroll
                for (int h = 0; h < 2; h++) {
                    int rr = trs[j] * 16 + lq + 8 * h;
                    int cn = tcs[j] * 16 + np * 8 + lr2;
                    float v0 = (cn     < rr) ? acc1[j][np][2*h]   : 0.f;
                    float v1 = (cn + 1 < rr) ? acc1[j][np][2*h+1] : 0.f;
                    *(uint32_t*)(sm + AT_PH + (rr * 136 + cn) * 2) = cvtH2(v0, v1);
                }
        }
    }
    if (ch > 0) CP_WAIT1();
    __syncthreads();

    // ======== Stage 2: D = QR @ S_pref (Q from persistent smem) ================
    float acc[2][8][4];
#pragma unroll
    for (int a = 0; a < 2; a++)
#pragma unroll
        for (int b = 0; b < 8; b++)
#pragma unroll
            for (int c = 0; c < 4; c++) acc[a][b][c] = 0.f;

    if (ch > 0) {
        for (int i = 0; i < 4; i++) {
            if (i >= 1 && i < 3) { cpS((i + 1) & 1, i + 1); CP_COMMIT(); }
            else if (i == 3) loadV3(0);
            uint32_t ab = sb + i * AT_QBUF;
            uint32_t bb = sb + AT_B0 + (i & 1) * AT_BUF_B;
#pragma unroll
            for (int k0 = 0; k0 < 64; k0 += 16) {
                uint32_t ah[2][4];
#pragma unroll
                for (int mt = 0; mt < 2; mt++) {
                    uint32_t off = (uint32_t)(((wm * 32 + mt * 16 + lm16) * 72 +
                                               k0 + 8 * l16) * 2);
                    ldsm4(ah[mt], ab + off);
                }
#pragma unroll
                for (int np = 0; np < 4; np++) {
                    uint32_t bh2[4];
                    uint32_t off = (uint32_t)(((k0 + lmod8 + 8 * l8) * 264 +
                                               wn * 64 + np * 16 + 8 * l16) * 2);
                    ldsm4t(bh2, bb + off);
#pragma unroll
                    for (int mt = 0; mt < 2; mt++) {
                        mma_f16(acc[mt][2*np],   ah[mt], bh2);
                        mma_f16(acc[mt][2*np+1], ah[mt], bh2 + 2);
                    }
                }
            }
            if (i < 3) { CP_WAIT0(); __syncthreads(); }
        }
        __syncthreads();
    }

    // ======== Stage 3: D += P @ V — skip slabs above warp's diagonal ===========
    storeV3(0);
    __syncthreads();
    for (int sl = 0; sl < 4; sl++) {
        if (sl < 3) loadV3(sl + 1);
        if (sl <= wm) {
            int s0 = sl * 32;
            uint32_t bb = sb + AT_B0 + (sl & 1) * AT_BUF_B;
#pragma unroll
            for (int k0 = 0; k0 < 32; k0 += 16) {
                uint32_t ah[2][4];
#pragma unroll
                for (int mt = 0; mt < 2; mt++) {
                    uint32_t off = (uint32_t)(((wm * 32 + mt * 16 + lm16) * 136 +
                                               s0 + k0 + 8 * l16) * 2);
                    ldsm4(ah[mt], sb + AT_PH + off);
                }
#pragma unroll
                for (int np = 0; np < 4; np++) {
                    uint32_t bh2[4];
                    uint32_t off = (uint32_t)(((k0 + lmod8 + 8 * l8) * 264 +
                                               wn * 64 + np * 16 + 8 * l16) * 2);
                    ldsm4t(bh2, bb + off);
#pragma unroll
                    for (int mt = 0; mt < 2; mt++) {
                        mma_f16(acc[mt][2*np],   ah[mt], bh2);
                        mma_f16(acc[mt][2*np+1], ah[mt], bh2 + 2);
                    }
                }
            }
        }
        if (sl < 3) { storeV3((sl + 1) & 1); __syncthreads(); }
    }

    // epilogue
#pragma unroll
    for (int mt = 0; mt < 2; mt++)
#pragma unroll
        for (int nt = 0; nt < 8; nt++)
#pragma unroll
            for (int h = 0; h < 2; h++) {
                int rr = wm * 32 + mt * 16 + lq + 8 * h;
                int cc = wn * 64 + nt * 8 + lr2;
                float2 o; o.x = acc[mt][nt][2*h]; o.y = acc[mt][nt][2*h+1];
                *(float2*)(out + (size_t)(bh * TT + t0 + rr) * NN + cc) = o;
            }
}

// ---------------- launcher -------------------------------------------------------
extern "C" void kernel_launch(void* const* d_in, const int* in_sizes, int n_in,
                              void* d_out, int out_size) {
    const float* Q = (const float*)d_in[0];
    const float* K = (const float*)d_in[1];
    const float* V = (const float*)d_in[2];
    float* out = (float*)d_out;

    static bool attr_set = false;
    if (!attr_set) {
        cudaFuncSetAttribute(k_kv,   cudaFuncAttributeMaxDynamicSharedMemorySize, SMEM_KV);
        cudaFuncSetAttribute(k_attn, cudaFuncAttributeMaxDynamicSharedMemorySize, SMEM_ATTN);
        attr_set = true;
    }

    k_tables<<<512, 512>>>();
    k_kv<<<BH * (NCH - 1), 512, SMEM_KV>>>(K, V);
    k_scan<<<(BH * NN * NN / 8 + 255) / 256, 256>>>();
    k_attn<<<BH * NCH, 512, SMEM_ATTN>>>(Q, K, V, out);
}

// round 17
// speedup vs baseline: 1.0315x; 1.0315x over previous
#include <cuda_runtime.h>
#include <cuda_fp16.h>
#include <math.h>
#include <stdint.h>

#define BH   24
#define TT   2048
#define NN   256
#define CC   128
#define NCH  16

// ---------------- device scratch ----------------------------------------------
__device__ float g_tabc[TT * (NN/2)];
__device__ float g_tabs[TT * (NN/2)];
__device__ __half g_S16[BH*NCH*NN*NN];        // per-chunk K^T V, fp16
__device__ __half g_Sh [BH*NCH*NN*NN];        // exclusive prefix, fp16

// ---------------- PTX helpers ---------------------------------------------------
__device__ __forceinline__ uint32_t smem_u32(const void* p) {
    uint32_t a;
    asm("{ .reg .u64 t; cvta.to.shared.u64 t, %1; cvt.u32.u64 %0, t; }" : "=r"(a) : "l"(p));
    return a;
}
__device__ __forceinline__ void cpa16(uint32_t s, const void* g) {
    asm volatile("cp.async.cg.shared.global [%0], [%1], 16;" :: "r"(s), "l"(g));
}
#define CP_COMMIT() asm volatile("cp.async.commit_group;" ::: "memory")
#define CP_WAIT0()  asm volatile("cp.async.wait_group 0;" ::: "memory")
#define CP_WAIT1()  asm volatile("cp.async.wait_group 1;" ::: "memory")

__device__ __forceinline__ void ldsm4(uint32_t* r, uint32_t a) {
    asm volatile("ldmatrix.sync.aligned.m8n8.x4.shared.b16 {%0,%1,%2,%3}, [%4];"
        : "=r"(r[0]), "=r"(r[1]), "=r"(r[2]), "=r"(r[3]) : "r"(a));
}
__device__ __forceinline__ void ldsm4t(uint32_t* r, uint32_t a) {
    asm volatile("ldmatrix.sync.aligned.m8n8.x4.trans.shared.b16 {%0,%1,%2,%3}, [%4];"
        : "=r"(r[0]), "=r"(r[1]), "=r"(r[2]), "=r"(r[3]) : "r"(a));
}
__device__ __forceinline__ void mma_f16(float* d, const uint32_t* a, const uint32_t* b) {
    asm volatile("mma.sync.aligned.m16n8k16.row.col.f32.f16.f16.f32 "
        "{%0,%1,%2,%3}, {%4,%5,%6,%7}, {%8,%9}, {%0,%1,%2,%3};"
        : "+f"(d[0]), "+f"(d[1]), "+f"(d[2]), "+f"(d[3])
        : "r"(a[0]), "r"(a[1]), "r"(a[2]), "r"(a[3]), "r"(b[0]), "r"(b[1]));
}

// ---------------- fp16 cvt helpers -----------------------------------------------
__device__ __forceinline__ uint32_t cvtH2(float x, float y) {
    __half2 H = __floats2half2_rn(x, y);
    return *(uint32_t*)&H;
}
__device__ __forceinline__ uint4 rope_cvt8_cs(const float* __restrict__ src,
                                              float4 c, float4 s) {
    float4 a = *(const float4*)(src);
    float4 b = *(const float4*)(src + 4);
    uint4 h;
    h.x = cvtH2(a.x*c.x - a.y*s.x, a.y*c.x + a.x*s.x);
    h.y = cvtH2(a.z*c.y - a.w*s.y, a.w*c.y + a.z*s.y);
    h.z = cvtH2(b.x*c.z - b.y*s.z, b.y*c.z + b.x*s.z);
    h.w = cvtH2(b.z*c.w - b.w*s.w, b.w*c.w + b.z*s.w);
    return h;
}
__device__ __forceinline__ uint4 rope_cvt8(const float* __restrict__ src, int t, int f) {
    float4 c = *(const float4*)(g_tabc + t * 128 + (f >> 1));
    float4 s = *(const float4*)(g_tabs + t * 128 + (f >> 1));
    return rope_cvt8_cs(src, c, s);
}
__device__ __forceinline__ uint4 cvt8(const float* __restrict__ src) {
    float4 a = *(const float4*)(src);
    float4 b = *(const float4*)(src + 4);
    uint4 h;
    h.x = cvtH2(a.x, a.y); h.y = cvtH2(a.z, a.w);
    h.z = cvtH2(b.x, b.y); h.w = cvtH2(b.z, b.w);
    return h;
}

// ---------------- kernel 1: RoPE phase tables -----------------------------------
__global__ void k_tables() {
    int id = blockIdx.x * blockDim.x + threadIdx.x;
    if (id >= TT * (NN/2)) return;
    int t = id >> 7;
    int j = id & 127;
    double fr_d = exp2(-(double)j / 8.0) / (2.0 * 3.14159265358979323846);
    float f32 = (float)fr_d;
    float ph  = (float)t * f32;
    ph = ph - floorf(ph);
    float ang = ph * 6.28318530717958647692f;
    double angd = (double)ang;
    g_tabc[id] = (float)cos(angd);
    g_tabs[id] = (float)sin(angd);
}

// ---------------- kernel 2: chunk KV state, V resident, split prologue ----------
#define KVV_SM   0
#define KVA_0    67584
#define KV_BUF_A 17408
#define SMEM_KV  102400

__global__ void __launch_bounds__(512, 1) k_kv(const float* __restrict__ K,
                                               const float* __restrict__ V) {
    extern __shared__ char sm[];
    uint32_t sb = smem_u32(sm);
    int tid = threadIdx.x, lane = tid & 31, wid = tid >> 5;
    int wm = wid >> 2, wn = wid & 3;
    int bx = blockIdx.x;
    int bh = bx / 15, ch = bx % 15;
    int t0 = ch * CC;
    int l16 = lane >> 4, lmod8 = lane & 7, l8 = (lane >> 3) & 1;
    int lq = lane >> 2, lr2 = (lane & 3) * 2;

    const float* Kp = K + (size_t)(bh * TT + t0) * NN;
    const float* Vp = V + (size_t)(bh * TT + t0) * NN;

    int ar = tid >> 4, ac8 = tid & 15;
    uint32_t a_so = (uint32_t)(ar * 272 + ac8 * 16);
    int vvr = tid >> 5, vvc = tid & 31;

    uint4 ah4a, ah4b;
    auto loadA = [&](int m0g, int sl) {
        int r0 = sl * 64;
        int f = m0g * 128 + ac8 * 8;
        ah4a = rope_cvt8(Kp + (size_t)(r0 + ar) * NN + f,      t0 + r0 + ar,      f);
        ah4b = rope_cvt8(Kp + (size_t)(r0 + ar + 32) * NN + f, t0 + r0 + ar + 32, f);
    };
    auto storeA = [&](int buf) {
        char* ab = sm + KVA_0 + buf * KV_BUF_A;
        *(uint4*)(ab + a_so) = ah4a;
        *(uint4*)(ab + 8704 + a_so) = ah4b;
    };

    loadA(0, 0);
    storeA(0);
#pragma unroll
    for (int g = 0; g < 4; g++) {
        int idx = tid + g * 512;
        int r = idx >> 5, c8 = idx & 31;
        uint4 vv = cvt8(Vp + (size_t)r * NN + c8 * 8);
        *(uint4*)(sm + KVV_SM + r * 528 + c8 * 16) = vv;
    }
    __syncthreads();

    float acc[2][8][4];
#pragma unroll
    for (int a = 0; a < 2; a++)
#pragma unroll
        for (int b = 0; b < 8; b++)
#pragma unroll
            for (int c = 0; c < 4; c++) acc[a][b][c] = 0.f;

    float4 vraw[8];
    for (int it = 0; it < 4; it++) {
        int m0g = it >> 1, sl = it & 1;
        if (it == 0) {
            loadA(0, 1);
#pragma unroll
            for (int g = 0; g < 4; g++) {
                int r = 64 + vvr + 16 * g;
                vraw[2*g]   = *(const float4*)(Vp + (size_t)r * NN + vvc * 8);
                vraw[2*g+1] = *(const float4*)(Vp + (size_t)r * NN + vvc * 8 + 4);
            }
        } else if (it < 3) loadA((it + 1) >> 1, (it + 1) & 1);
        uint32_t ab = sb + KVA_0 + (it & 1) * KV_BUF_A;
#pragma unroll
        for (int k0 = 0; k0 < 64; k0 += 16) {
            uint32_t ah[2][4];
#pragma unroll
            for (int mt = 0; mt < 2; mt++) {
                uint32_t off = (uint32_t)(((k0 + lmod8 + 8 * l16) * 136 +
                                           wm * 32 + mt * 16 + 8 * l8) * 2);
                ldsm4t(ah[mt], ab + off);
            }
#pragma unroll
            for (int np = 0; np < 4; np++) {
                uint32_t bh2[4];
                uint32_t off = (uint32_t)(((sl * 64 + k0 + lmod8 + 8 * l8) * 264 +
                                           wn * 64 + np * 16 + 8 * l16) * 2);
                ldsm4t(bh2, sb + KVV_SM + off);
#pragma unroll
                for (int mt = 0; mt < 2; mt++) {
                    mma_f16(acc[mt][2*np],   ah[mt], bh2);
                    mma_f16(acc[mt][2*np+1], ah[mt], bh2 + 2);
                }
            }
        }
        if (sl == 1) {
            __half* Sp = g_S16 + (size_t)(bh * NCH + ch) * (NN * NN);
#pragma unroll
            for (int mt = 0; mt < 2; mt++)
#pragma unroll
                for (int nt = 0; nt < 8; nt++)
#pragma unroll
                    for (int h = 0; h < 2; h++) {
                        int rr = m0g * 128 + wm * 32 + mt * 16 + lq + 8 * h;
                        int cc = wn * 64 + nt * 8 + lr2;
                        *(uint32_t*)(Sp + (size_t)rr * NN + cc) =
                            cvtH2(acc[mt][nt][2*h], acc[mt][nt][2*h+1]);
                    }
#pragma unroll
            for (int a = 0; a < 2; a++)
#pragma unroll
                for (int b = 0; b < 8; b++)
#pragma unroll
                    for (int c = 0; c < 4; c++) acc[a][b][c] = 0.f;
        }
        if (it == 0) {
#pragma unroll
            for (int g = 0; g < 4; g++) {
                int r = 64 + vvr + 16 * g;
                uint4 vv;
                vv.x = cvtH2(vraw[2*g].x,   vraw[2*g].y);
                vv.y = cvtH2(vraw[2*g].z,   vraw[2*g].w);
                vv.z = cvtH2(vraw[2*g+1].x, vraw[2*g+1].y);
                vv.w = cvtH2(vraw[2*g+1].z, vraw[2*g+1].w);
                *(uint4*)(sm + KVV_SM + r * 528 + vvc * 16) = vv;
            }
            storeA(1);
            __syncthreads();
        } else if (it < 3) { storeA((it + 1) & 1); __syncthreads(); }
    }
}

// ---------------- kernel 3: exclusive prefix scan (uint4, fp32 accum) -----------
__global__ void k_scan() {
    int g = blockIdx.x * blockDim.x + threadIdx.x;
    if (g >= BH * NN * NN / 8) return;
    int bh = g >> 13;
    int e8 = (g & 8191) << 3;
    size_t base = (size_t)bh * NCH * (NN * NN) + e8;
    uint4 vals[NCH - 1];
#pragma unroll
    for (int i = 0; i < NCH - 1; i++)
        vals[i] = *(const uint4*)(g_S16 + base + (size_t)i * (NN * NN));
    float r[8];
#pragma unroll
    for (int j = 0; j < 8; j++) r[j] = 0.f;
#pragma unroll
    for (int i = 0; i < NCH; i++) {
        size_t p = base + (size_t)i * (NN * NN);
        uint4 H;
        H.x = cvtH2(r[0], r[1]); H.y = cvtH2(r[2], r[3]);
        H.z = cvtH2(r[4], r[5]); H.w = cvtH2(r[6], r[7]);
        *(uint4*)(g_Sh + p) = H;
        if (i < NCH - 1) {
            float2 a0 = __half22float2(*(__half2*)&vals[i].x);
            float2 a1 = __half22float2(*(__half2*)&vals[i].y);
            float2 a2 = __half22float2(*(__half2*)&vals[i].z);
            float2 a3 = __half22float2(*(__half2*)&vals[i].w);
            r[0] += a0.x; r[1] += a0.y; r[2] += a1.x; r[3] += a1.y;
            r[4] += a2.x; r[5] += a2.y; r[6] += a3.x; r[7] += a3.y;
        }
    }
}

// ---------------- kernel 4: Out = QR@S_pref + strict_tril(QR@KR^T)@V ------------
// Q persistent (4 x 18432 at offset 0); stage 3 re-uses the Q region for resident V.
#define AT_QBUF  18432
#define AT_B0    73728
#define AT_BUF_B 33792
#define AT_PH    141312
#define SMEM_ATTN 176128

#define S1_R_PACK 981476u
#define S1_C_PACK 54436u

__global__ void __launch_bounds__(512, 1) k_attn(const float* __restrict__ Q,
                                                 const float* __restrict__ K,
                                                 const float* __restrict__ V,
                                                 float* __restrict__ out) {
    extern __shared__ char sm[];
    uint32_t sb = smem_u32(sm);
    int tid = threadIdx.x, lane = tid & 31, wid = tid >> 5;
    int wm = wid >> 2, wn = wid & 3;
    int bh = blockIdx.x >> 4, ch = 15 - (blockIdx.x & 15);
    int t0 = ch * CC;
    int lm16 = lane & 15, l16 = lane >> 4, lmod8 = lane & 7, l8 = (lane >> 3) & 1;
    int lq = lane >> 2, lr2 = (lane & 3) * 2;

    const float* Qp = Q + (size_t)(bh * TT + t0) * NN;
    const float* Kp = K + (size_t)(bh * TT + t0) * NN;
    const float* Vp = V + (size_t)(bh * TT + t0) * NN;
    const __half* Sh = g_Sh + (size_t)(bh * NCH + ch) * (NN * NN);

    int sr = tid >> 2, sc8 = tid & 3;
    uint32_t s_so1 = (uint32_t)((sr * 72 + sc8 * 8) * 2);
    uint32_t s_so2 = (uint32_t)((sr * 72 + 32 + sc8 * 8) * 2);

    uint4 qa, qb, ka, kb;
    auto loadQK = [&](int sl) {
        int f1 = sl * 64 + sc8 * 8;
        float4 c1 = *(const float4*)(g_tabc + (t0 + sr) * 128 + (f1 >> 1));
        float4 s1 = *(const float4*)(g_tabs + (t0 + sr) * 128 + (f1 >> 1));
        float4 c2 = *(const float4*)(g_tabc + (t0 + sr) * 128 + (f1 >> 1) + 16);
        float4 s2 = *(const float4*)(g_tabs + (t0 + sr) * 128 + (f1 >> 1) + 16);
        qa = rope_cvt8_cs(Qp + (size_t)sr * NN + f1, c1, s1);
        qb = rope_cvt8_cs(Qp + (size_t)sr * NN + f1 + 32, c2, s2);
        ka = rope_cvt8_cs(Kp + (size_t)sr * NN + f1, c1, s1);
        kb = rope_cvt8_cs(Kp + (size_t)sr * NN + f1 + 32, c2, s2);
    };
    auto storeQK = [&](int sl) {
        char* qbuf = sm + sl * AT_QBUF;
        *(uint4*)(qbuf + s_so1) = qa;
        *(uint4*)(qbuf + s_so2) = qb;
        char* kbuf = sm + AT_B0 + (sl & 1) * AT_BUF_B;
        *(uint4*)(kbuf + s_so1) = ka;
        *(uint4*)(kbuf + s_so2) = kb;
    };
    auto cpS = [&](int buf, int sl) {
        uint32_t bb = sb + AT_B0 + buf * AT_BUF_B;
        int f0 = sl * 64;
#pragma unroll
        for (int v = tid; v < 2048; v += 512) {
            int r = v >> 5, c8 = v & 31;
            uint32_t so = (uint32_t)(r * 528 + c8 * 16);
            cpa16(bb + so, Sh + (size_t)(f0 + r) * NN + c8 * 8);
        }
    };

    int pr = (S1_R_PACK >> (wid * 2)) & 3;
    int pc = (S1_C_PACK >> (wid * 2)) & 3;
    bool act1 = (wid < 10);

    // ======== Stage 1: P = QR @ KR^T, lower-triangle 32x32 tiles ===============
    float acc1[2][4][4];
#pragma unroll
    for (int a = 0; a < 2; a++)
#pragma unroll
        for (int b = 0; b < 4; b++)
#pragma unroll
            for (int c = 0; c < 4; c++) acc1[a][b][c] = 0.f;

    loadQK(0);
    storeQK(0);
    __syncthreads();
    for (int sl = 0; sl < 4; sl++) {
        if (sl < 3) loadQK(sl + 1);
        else if (ch > 0) { cpS(0, 0); CP_COMMIT(); }
        if (act1) {
            uint32_t ab = sb + sl * AT_QBUF;
            uint32_t bb = sb + AT_B0 + (sl & 1) * AT_BUF_B;
#pragma unroll
            for (int k0 = 0; k0 < 64; k0 += 16) {
                uint32_t ah[2][4];
#pragma unroll
                for (int mt = 0; mt < 2; mt++) {
                    uint32_t off = (uint32_t)(((pr * 32 + mt * 16 + lm16) * 72 +
                                               k0 + 8 * l16) * 2);
                    ldsm4(ah[mt], ab + off);
                }
#pragma unroll
                for (int np = 0; np < 2; np++) {
                    uint32_t bh2[4];
                    uint32_t off = (uint32_t)(((pc * 32 + np * 16 + lmod8 + 8 * l16) * 72 +
                                               k0 + 8 * l8) * 2);
                    ldsm4(bh2, bb + off);
#pragma unroll
                    for (int mt = 0; mt < 2; mt++) {
                        mma_f16(acc1[mt][2*np],   ah[mt], bh2);
                        mma_f16(acc1[mt][2*np+1], ah[mt], bh2 + 2);
                    }
                }
            }
        }
        if (sl < 3) { storeQK(sl + 1); __syncthreads(); }
    }
    __syncthreads();
    if (ch > 0) { cpS(1, 1); CP_COMMIT(); }

    // mask (strict lower triangle) + fp16 cvt into smem P
    if (act1) {
#pragma unroll
        for (int mt = 0; mt < 2; mt++)
#pragma unroll
            for (int nt = 0; nt < 4; nt++)
#pragma unroll
                for (int h = 0; h < 2; h++) {
                    int rr = pr * 32 + mt * 16 + lq + 8 * h;
                    int cn = pc * 32 + nt * 8 + lr2;
                    float v0 = (cn     < rr) ? acc1[mt][nt][2*h]   : 0.f;
                    float v1 = (cn + 1 < rr) ? acc1[mt][nt][2*h+1] : 0.f;
                    *(uint32_t*)(sm + AT_PH + (rr * 136 + cn) * 2) = cvtH2(v0, v1);
                }
    }
    if (ch > 0) CP_WAIT1();
    __syncthreads();

    // ======== Stage 2: D = QR @ S_pref (Q from persistent smem) ================
    float acc[2][8][4];
#pragma unroll
    for (int a = 0; a < 2; a++)
#pragma unroll
        for (int b = 0; b < 8; b++)
#pragma unroll
            for (int c = 0; c < 4; c++) acc[a][b][c] = 0.f;

    if (ch > 0) {
        for (int i = 0; i < 4; i++) {
            if (i >= 1 && i < 3) { cpS((i + 1) & 1, i + 1); CP_COMMIT(); }
            uint32_t ab = sb + i * AT_QBUF;
            uint32_t bb = sb + AT_B0 + (i & 1) * AT_BUF_B;
#pragma unroll
            for (int k0 = 0; k0 < 64; k0 += 16) {
                uint32_t ah[2][4];
#pragma unroll
                for (int mt = 0; mt < 2; mt++) {
                    uint32_t off = (uint32_t)(((wm * 32 + mt * 16 + lm16) * 72 +
                                               k0 + 8 * l16) * 2);
                    ldsm4(ah[mt], ab + off);
                }
#pragma unroll
                for (int np = 0; np < 4; np++) {
                    uint32_t bh2[4];
                    uint32_t off = (uint32_t)(((k0 + lmod8 + 8 * l8) * 264 +
                                               wn * 64 + np * 16 + 8 * l16) * 2);
                    ldsm4t(bh2, bb + off);
#pragma unroll
                    for (int mt = 0; mt < 2; mt++) {
                        mma_f16(acc[mt][2*np],   ah[mt], bh2);
                        mma_f16(acc[mt][2*np+1], ah[mt], bh2 + 2);
                    }
                }
            }
            if (i < 3) { CP_WAIT0(); __syncthreads(); }
        }
        __syncthreads();                   // Q region dead after this
    }

    // ======== Stage 3: V resident in dead Q region; no inner barriers ==========
    {
        int vvr = tid >> 5, vvc = tid & 31;
#pragma unroll
        for (int g = 0; g < 8; g++) {
            int r = vvr + 16 * g;
            uint4 vv = cvt8(Vp + (size_t)r * NN + vvc * 8);
            *(uint4*)(sm + r * 528 + vvc * 16) = vv;
        }
    }
    __syncthreads();

    for (int sl = 0; sl <= wm; sl++) {
        int s0 = sl * 32;
#pragma unroll
        for (int k0 = 0; k0 < 32; k0 += 16) {
            uint32_t ah[2][4];
#pragma unroll
            for (int mt = 0; mt < 2; mt++) {
                uint32_t off = (uint32_t)(((wm * 32 + mt * 16 + lm16) * 136 +
                                           s0 + k0 + 8 * l16) * 2);
                ldsm4(ah[mt], sb + AT_PH + off);
            }
#pragma unroll
            for (int np = 0; np < 4; np++) {
                uint32_t bh2[4];
                uint32_t off = (uint32_t)(((s0 + k0 + lmod8 + 8 * l8) * 264 +
                                           wn * 64 + np * 16 + 8 * l16) * 2);
                ldsm4t(bh2, sb + off);
#pragma unroll
                for (int mt = 0; mt < 2; mt++) {
                    mma_f16(acc[mt][2*np],   ah[mt], bh2);
                    mma_f16(acc[mt][2*np+1], ah[mt], bh2 + 2);
                }
            }
        }
    }

    // epilogue
#pragma unroll
    for (int mt = 0; mt < 2; mt++)
#pragma unroll
        for (int nt = 0; nt < 8; nt++)
#pragma unroll
            for (int h = 0; h < 2; h++) {
                int rr = wm * 32 + mt * 16 + lq + 8 * h;
                int cc = wn * 64 + nt * 8 + lr2;
                float2 o; o.x = acc[mt][nt][2*h]; o.y = acc[mt][nt][2*h+1];
                *(float2*)(out + (size_t)(bh * TT + t0 + rr) * NN + cc) = o;
            }
}

// ---------------- launcher -------------------------------------------------------
extern "C" void kernel_launch(void* const* d_in, const int* in_sizes, int n_in,
                              void* d_out, int out_size) {
    const float* Q = (const float*)d_in[0];
    const float* K = (const float*)d_in[1];
    const float* V = (const float*)d_in[2];
    float* out = (float*)d_out;

    static bool attr_set = false;
    if (!attr_set) {
        cudaFuncSetAttribute(k_kv,   cudaFuncAttributeMaxDynamicSharedMemorySize, SMEM_KV);
        cudaFuncSetAttribute(k_attn, cudaFuncAttributeMaxDynamicSharedMemorySize, SMEM_ATTN);
        attr_set = true;
    }

    k_tables<<<512, 512>>>();
    k_kv<<<BH * (NCH - 1), 512, SMEM_KV>>>(K, V);
    k_scan<<<(BH * NN * NN / 8 + 255) / 256, 256>>>();
    k_attn<<<BH * NCH, 512, SMEM_ATTN>>>(Q, K, V, out);
}